// round 15
// baseline (speedup 1.0000x reference)
#include <cuda_runtime.h>

// SpikeCNN fused: one block = one image, all 8 timesteps, warp-specialized.
// R15 = R14 structure with warp-3 fixed:
//   warps 0-2: conv2 oc-pair, packed cols j=0..5 (450 FFMA2, 6 indep chains)
//   warp 3:    conv2 packed col j=6 for ALL 3 oc-pairs with INTERLEAVED
//              accumulator chains (G0,G1,G2) + hoisted weight sets,
//              + fc/mem3 (phase D, pipelined t-1; mem3/acc3 in SMEM)
//   warps 4-6: phase A (mem1+pool, one channel each)
//   fma.rn.f32x2, zero packing overhead; 1 barrier/step; bitwise-exact.

#define TH 1.0f
#define TSTEPS 8
#define NT 224
#define XPITCH 33           // xpadT: col*33 + row (col-major)
#define C1CP 30             // c1s: c*840 + col*30 + row (col-major)
#define P1K 14              // k slots per row (k 0..10 used; pitch 14 float2)
#define P1ROWS 18           // padded pooled rows
#define P1SZ (3 * P1ROWS * P1K)   // float2 elements per buffer

__device__ __forceinline__ unsigned long long pk2(float lo, float hi) {
    unsigned long long r;
    asm("mov.b64 %0, {%1,%2};" : "=l"(r) : "f"(lo), "f"(hi));
    return r;
}
__device__ __forceinline__ void fma2(unsigned long long& acc,
                                     unsigned long long a, unsigned long long b) {
    asm("fma.rn.f32x2 %0, %1, %2, %0;" : "+l"(acc) : "l"(a), "l"(b));
}
__device__ __forceinline__ float2 upk(unsigned long long v) {
    float2 r;
    asm("mov.b64 {%0,%1}, %2;" : "=f"(r.x), "=f"(r.y) : "l"(v));
    return r;
}

__global__ __launch_bounds__(NT, 4)
void snn_kernel(const float* __restrict__ x,
                const float* __restrict__ w1, const float* __restrict__ b1,
                const float* __restrict__ w2, const float* __restrict__ b2,
                const float* __restrict__ wf, const float* __restrict__ bf,
                float* __restrict__ out, int nb)
{
    __shared__ __align__(16) float  xpadT[32 * XPITCH];   // 4224 B
    __shared__ __align__(16) float  c1s[3 * 28 * C1CP];   // 10080 B (col-major)
    __shared__ __align__(16) float2 p1p[2][P1SZ];         // 12096 B, double-buffered
    __shared__ __align__(16) float2 w2q[90 * 6];          // (w,w) rows, pitch 6
    __shared__ __align__(16) float  s2P[2][6 * 196];      // 9408 B [oc][grp][4]
    __shared__ float m3s[10], a3s[10];                    // warp-3 fc state

    const int tid  = threadIdx.x;
    const int warp = tid >> 5;              // 0..6
    const int lane = tid & 31;
    const int b    = blockIdx.x;

    // ---- init ----
    for (int i = tid; i < 32 * XPITCH; i += NT) xpadT[i] = 0.f;
    for (int i = tid; i < 2 * P1SZ; i += NT)    p1p[0][i] = make_float2(0.f, 0.f);
    for (int i = tid; i < 90 * 6; i += NT)      w2q[i]   = make_float2(0.f, 0.f);
    if (tid < 10) { m3s[tid] = 0.f; a3s[tid] = 0.f; }
    __syncthreads();
    // w2 flat: i = g*5 + dj with g = (oc*3+ic)*5+di
    for (int i = tid; i < 450; i += NT) {
        int g = i / 5, dj = i - 5 * g;
        float w = w2[i];
        w2q[g * 6 + dj] = make_float2(w, w);
    }
    const float* xb = x + (size_t)b * 784;
    for (int i = tid; i < 784; i += NT) {
        int r = i / 28, c = i % 28;
        xpadT[(c + 2) * XPITCH + (r + 2)] = xb[i];
    }
    __syncthreads();

    // ---- conv1 (once): warps 0..5 ----
    if (warp < 6 && lane < 28) {
        int c = warp % 3, colbase = (warp / 3) * 14, row = lane;
        float wr[25];
        #pragma unroll
        for (int k = 0; k < 25; k++) wr[k] = __ldg(&w1[c * 25 + k]);
        float bias = __ldg(&b1[c]);
        float acc[14];
        #pragma unroll
        for (int j = 0; j < 14; j++) acc[j] = bias;
        #pragma unroll
        for (int di = 0; di < 5; di++) {
            float v[18];
            #pragma unroll
            for (int k = 0; k < 18; k++)
                v[k] = xpadT[(colbase + k) * XPITCH + row + di];
            #pragma unroll
            for (int j = 0; j < 14; j++)
                #pragma unroll
                for (int dj = 0; dj < 5; dj++)
                    acc[j] += v[j + dj] * wr[di * 5 + dj];
        }
        #pragma unroll
        for (int j = 0; j < 14; j++)
            c1s[c * 840 + (colbase + j) * C1CP + row] = acc[j];
    }
    __syncthreads();   // c1s complete before phase A reads it

    // ---- persistent register state ----
    const int  par  = lane & 1;             // oc parity within a pair
    const int  brow = lane >> 1;            // conv2 output row (0..13)
    // B warps 0..2: oc = 2*warp + par, packed cols j = 0..5
    const bool bwarp = (warp < 3);
    const bool bact  = bwarp && (lane < 28);
    const int  boc   = 2 * warp + par;
    float m2x[6], m2y[6];
    #pragma unroll
    for (int j = 0; j < 6; j++) { m2x[j] = 0.f; m2y[j] = 0.f; }
    const float b2r = bact ? __ldg(&b2[boc]) : 0.f;
    // warp 3: j=6 slice for all 3 oc-pairs + D
    const bool j6act = (warp == 3) && (lane < 28);
    float m36x[3], m36y[3], b2p[3];
    #pragma unroll
    for (int p = 0; p < 3; p++) {
        m36x[p] = 0.f; m36y[p] = 0.f;
        b2p[p] = j6act ? __ldg(&b2[2 * p + par]) : 0.f;
    }
    // A warps 4..6: channel c = warp-4, mem1 in regs
    const int  ach = warp - 4;
    float mr[28];
    #pragma unroll
    for (int i = 0; i < 28; i++) mr[i] = 0.f;
    const int  pi  = lane % 14;
    const int  dpj = lane / 14;
    const bool aact = (warp >= 4) && (lane < 28);

    // Phase A: mem1 += c1, fire, 2x2 pool -> p1p[pb] paired layout
    auto phaseA = [&](int pb) {
        if (aact) {
            float* p1f = reinterpret_cast<float*>(p1p[pb]);
            #pragma unroll
            for (int i = 0; i < 7; i++) {
                int pj   = 2 * i + dpj;                 // pooled col 0..13
                int base = ach * 840 + (2 * pj) * C1CP + 2 * pi;
                float2 ca = *reinterpret_cast<const float2*>(&c1s[base]);
                float2 cb = *reinterpret_cast<const float2*>(&c1s[base + C1CP]);
                float m0 = mr[i * 4 + 0] + ca.x;
                float m1 = mr[i * 4 + 1] + ca.y;
                float m2 = mr[i * 4 + 2] + cb.x;
                float m3v = mr[i * 4 + 3] + cb.y;
                float s0 = (m0 >= TH) ? TH : 0.f;
                float s1 = (m1 >= TH) ? TH : 0.f;
                float s2 = (m2 >= TH) ? TH : 0.f;
                float s3 = (m3v >= TH) ? TH : 0.f;
                mr[i * 4 + 0] = m0 - s0;
                mr[i * 4 + 1] = m1 - s1;
                mr[i * 4 + 2] = m2 - s2;
                mr[i * 4 + 3] = m3v - s3;
                float val = 0.25f * (s0 + s1 + s2 + s3);
                int padcol = pj + 2;                    // 2..15
                int rbase  = (ach * P1ROWS + (pi + 2)) * P1K;
                if (padcol <= 13) p1f[(rbase + padcol) * 2]         = val;  // .x
                if (padcol >= 7)  p1f[(rbase + padcol - 7) * 2 + 1] = val;  // .y
            }
        }
    };

    // Phase D (warp 3): fc + mem3 fire for timestep td; mem3/acc3 in SMEM
    auto phaseD = [&](int td) {
        const float* buf = s2P[td & 1];
        float pv[10];
        #pragma unroll
        for (int i = 0; i < 10; i++) {
            int k = lane + 32 * i;
            if (k < 294) {
                float4 q = *reinterpret_cast<const float4*>(&buf[k * 4]);
                pv[i] = 0.25f * (q.x + q.y + q.z + q.w);
            } else pv[i] = 0.f;
        }
        #pragma unroll
        for (int r = 0; r < 10; r++) {
            float part = 0.f;
            const float* wrow = wf + r * 294;
            #pragma unroll
            for (int i = 0; i < 10; i++) {
                int k = lane + 32 * i;
                if (k < 294) part += pv[i] * __ldg(&wrow[k]);
            }
            #pragma unroll
            for (int s = 16; s > 0; s >>= 1)
                part += __shfl_xor_sync(0xffffffffu, part, s);
            float m  = m3s[r] + part + __ldg(&bf[r]);
            float sp = (m >= TH) ? TH : 0.f;
            float a  = a3s[r] + sp;
            if (lane == 0) {
                m3s[r] = m - sp;
                a3s[r] = a;
                if (td == 3) out[(size_t)b * 10 + r] = a * 0.25f;
                if (td == 7) out[(size_t)nb * 10 + (size_t)b * 10 + r] = a * 0.125f;
            }
        }
    };

    phaseA(0);           // p1 for t=0 (warps 4-6)
    __syncthreads();

    // ---- pipelined time loop: ONE barrier per timestep ----
    for (int t = 0; t < TSTEPS; t++) {
        if (bwarp) {
            // B(t) cols j=0..5: reads p1p[t&1], writes s2P[t&1]
            if (lane < 28) {
                const float2* p1 = p1p[t & 1];
                unsigned long long A2[6];
                unsigned long long bini = pk2(b2r, b2r);
                #pragma unroll
                for (int j = 0; j < 6; j++) A2[j] = bini;
                #pragma unroll
                for (int ic = 0; ic < 3; ic++) {
                    #pragma unroll
                    for (int di = 0; di < 5; di++) {
                        const float2* src = &p1[(ic * P1ROWS + brow + di) * P1K];
                        ulonglong2 u0 = *reinterpret_cast<const ulonglong2*>(src);
                        ulonglong2 u1 = *reinterpret_cast<const ulonglong2*>(src + 2);
                        ulonglong2 u2 = *reinterpret_cast<const ulonglong2*>(src + 4);
                        ulonglong2 u3 = *reinterpret_cast<const ulonglong2*>(src + 6);
                        ulonglong2 u4 = *reinterpret_cast<const ulonglong2*>(src + 8);
                        unsigned long long pv[10] = {u0.x, u0.y, u1.x, u1.y, u2.x,
                                                     u2.y, u3.x, u3.y, u4.x, u4.y};
                        const int g = (boc * 3 + ic) * 5 + di;
                        const float2* wp = &w2q[g * 6];
                        ulonglong2 wA = *reinterpret_cast<const ulonglong2*>(wp);
                        ulonglong2 wB = *reinterpret_cast<const ulonglong2*>(wp + 2);
                        unsigned long long w4v =
                            *reinterpret_cast<const unsigned long long*>(wp + 4);
                        unsigned long long wv[5] = {wA.x, wA.y, wB.x, wB.y, w4v};
                        #pragma unroll
                        for (int dj = 0; dj < 5; dj++)
                            #pragma unroll
                            for (int j = 0; j < 6; j++)
                                fma2(A2[j], pv[j + dj], wv[dj]);
                    }
                }
                float* sdst = s2P[t & 1];
                const int obase = boc * 196;
                #pragma unroll
                for (int j = 0; j < 6; j++) {
                    float2 q = upk(A2[j]);
                    {
                        float m  = m2x[j] + q.x;
                        float sp = (m >= TH) ? TH : 0.f;
                        m2x[j]   = m - sp;
                        int cc = j;
                        sdst[obase + ((brow >> 1) * 7 + (cc >> 1)) * 4 +
                             (brow & 1) * 2 + (cc & 1)] = sp;
                    }
                    {
                        float m  = m2y[j] + q.y;
                        float sp = (m >= TH) ? TH : 0.f;
                        m2y[j]   = m - sp;
                        int cc = j + 7;
                        sdst[obase + ((brow >> 1) * 7 + (cc >> 1)) * 4 +
                             (brow & 1) * 2 + (cc & 1)] = sp;
                    }
                }
            }
        } else if (warp == 3) {
            // B(t) col j=6 for all 3 oc-pairs — interleaved chains, hoisted weights
            if (j6act) {
                const float2* p1 = p1p[t & 1];
                unsigned long long G0 = pk2(b2p[0], b2p[0]);
                unsigned long long G1 = pk2(b2p[1], b2p[1]);
                unsigned long long G2 = pk2(b2p[2], b2p[2]);
                #pragma unroll
                for (int ic = 0; ic < 3; ic++) {
                    #pragma unroll
                    for (int di = 0; di < 5; di++) {
                        const float2* src = &p1[(ic * P1ROWS + brow + di) * P1K];
                        ulonglong2 u3 = *reinterpret_cast<const ulonglong2*>(src + 6);
                        ulonglong2 u4 = *reinterpret_cast<const ulonglong2*>(src + 8);
                        unsigned long long p10 =
                            *reinterpret_cast<const unsigned long long*>(src + 10);
                        unsigned long long pv6[5] = {u3.x, u3.y, u4.x, u4.y, p10};
                        unsigned long long wv0[5], wv1[5], wv2[5];
                        {
                            const float2* wp0 = &w2q[(((par)     * 3 + ic) * 5 + di) * 6];
                            const float2* wp1 = &w2q[(((2 + par) * 3 + ic) * 5 + di) * 6];
                            const float2* wp2 = &w2q[(((4 + par) * 3 + ic) * 5 + di) * 6];
                            ulonglong2 a0 = *reinterpret_cast<const ulonglong2*>(wp0);
                            ulonglong2 b0 = *reinterpret_cast<const ulonglong2*>(wp0 + 2);
                            wv0[0]=a0.x; wv0[1]=a0.y; wv0[2]=b0.x; wv0[3]=b0.y;
                            wv0[4]=*reinterpret_cast<const unsigned long long*>(wp0 + 4);
                            ulonglong2 a1 = *reinterpret_cast<const ulonglong2*>(wp1);
                            ulonglong2 b1v = *reinterpret_cast<const ulonglong2*>(wp1 + 2);
                            wv1[0]=a1.x; wv1[1]=a1.y; wv1[2]=b1v.x; wv1[3]=b1v.y;
                            wv1[4]=*reinterpret_cast<const unsigned long long*>(wp1 + 4);
                            ulonglong2 a2 = *reinterpret_cast<const ulonglong2*>(wp2);
                            ulonglong2 b2v = *reinterpret_cast<const ulonglong2*>(wp2 + 2);
                            wv2[0]=a2.x; wv2[1]=a2.y; wv2[2]=b2v.x; wv2[3]=b2v.y;
                            wv2[4]=*reinterpret_cast<const unsigned long long*>(wp2 + 4);
                        }
                        #pragma unroll
                        for (int dj = 0; dj < 5; dj++) {
                            fma2(G0, pv6[dj], wv0[dj]);   // 3 independent chains
                            fma2(G1, pv6[dj], wv1[dj]);
                            fma2(G2, pv6[dj], wv2[dj]);
                        }
                    }
                }
                float* sdst = s2P[t & 1];
                unsigned long long Gs[3] = {G0, G1, G2};
                #pragma unroll
                for (int p = 0; p < 3; p++) {
                    const int oc = 2 * p + par;
                    const int obase = oc * 196;
                    float2 q = upk(Gs[p]);
                    {
                        float m  = m36x[p] + q.x;
                        float sp = (m >= TH) ? TH : 0.f;
                        m36x[p]  = m - sp;
                        // cc = 6
                        sdst[obase + ((brow >> 1) * 7 + 3) * 4 +
                             (brow & 1) * 2 + 0] = sp;
                    }
                    {
                        float m  = m36y[p] + q.y;
                        float sp = (m >= TH) ? TH : 0.f;
                        m36y[p]  = m - sp;
                        // cc = 13
                        sdst[obase + ((brow >> 1) * 7 + 6) * 4 +
                             (brow & 1) * 2 + 1] = sp;
                    }
                }
            }
            if (t > 0) phaseD(t - 1);
        } else {
            if (t < TSTEPS - 1) phaseA((t + 1) & 1);
        }
        __syncthreads();
    }
    // epilogue: D for the last timestep
    if (warp == 3) phaseD(TSTEPS - 1);
}

extern "C" void kernel_launch(void* const* d_in, const int* in_sizes, int n_in,
                              void* d_out, int out_size)
{
    const float* x  = (const float*)d_in[0];
    const float* w1 = (const float*)d_in[1];
    const float* b1 = (const float*)d_in[2];
    const float* w2 = (const float*)d_in[3];
    const float* b2 = (const float*)d_in[4];
    const float* wf = (const float*)d_in[5];
    const float* bf = (const float*)d_in[6];
    float* out = (float*)d_out;

    int nb = in_sizes[0] / 784;   // 4096
    snn_kernel<<<nb, NT>>>(x, w1, b1, w2, b2, wf, bf, out, nb);
}

// round 17
// speedup vs baseline: 1.2799x; 1.2799x over previous
#include <cuda_runtime.h>

// SpikeCNN fused: one block = one image, all 8 timesteps, warp-specialized.
// R17 = R16 resubmitted verbatim (R16 bench was a broker infra failure).
//   warps 0-2: conv2 oc-pair, packed cols j=0..5 (450 FFMA2)
//   warp 3:    ONLY conv2 packed col j=6 for all 3 oc-pairs (interleaved chains)
//   warps 4-6: phase A  +  phase D(t-1) split by fc-row (4/4/2 rows, regs state)
//   fma.rn.f32x2 zero-overhead packing; 1 barrier/step; bitwise-exact.

#define TH 1.0f
#define TSTEPS 8
#define NT 224
#define XPITCH 33           // xpadT: col*33 + row (col-major)
#define C1CP 30             // c1s: c*840 + col*30 + row (col-major)
#define P1K 14              // k slots per row (k 0..10 used; pitch 14 float2)
#define P1ROWS 18           // padded pooled rows
#define P1SZ (3 * P1ROWS * P1K)   // float2 elements per buffer

__device__ __forceinline__ unsigned long long pk2(float lo, float hi) {
    unsigned long long r;
    asm("mov.b64 %0, {%1,%2};" : "=l"(r) : "f"(lo), "f"(hi));
    return r;
}
__device__ __forceinline__ void fma2(unsigned long long& acc,
                                     unsigned long long a, unsigned long long b) {
    asm("fma.rn.f32x2 %0, %1, %2, %0;" : "+l"(acc) : "l"(a), "l"(b));
}
__device__ __forceinline__ float2 upk(unsigned long long v) {
    float2 r;
    asm("mov.b64 {%0,%1}, %2;" : "=f"(r.x), "=f"(r.y) : "l"(v));
    return r;
}

__global__ __launch_bounds__(NT, 4)
void snn_kernel(const float* __restrict__ x,
                const float* __restrict__ w1, const float* __restrict__ b1,
                const float* __restrict__ w2, const float* __restrict__ b2,
                const float* __restrict__ wf, const float* __restrict__ bf,
                float* __restrict__ out, int nb)
{
    __shared__ __align__(16) float  xpadT[32 * XPITCH];   // 4224 B
    __shared__ __align__(16) float  c1s[3 * 28 * C1CP];   // 10080 B (col-major)
    __shared__ __align__(16) float2 p1p[2][P1SZ];         // 12096 B, double-buffered
    __shared__ __align__(16) float2 w2q[90 * 6];          // (w,w) rows, pitch 6
    __shared__ __align__(16) float  s2P[2][6 * 196];      // 9408 B [oc][grp][4]

    const int tid  = threadIdx.x;
    const int warp = tid >> 5;              // 0..6
    const int lane = tid & 31;
    const int b    = blockIdx.x;

    // ---- init ----
    for (int i = tid; i < 32 * XPITCH; i += NT) xpadT[i] = 0.f;
    for (int i = tid; i < 2 * P1SZ; i += NT)    p1p[0][i] = make_float2(0.f, 0.f);
    for (int i = tid; i < 90 * 6; i += NT)      w2q[i]   = make_float2(0.f, 0.f);
    __syncthreads();
    // w2 flat: i = g*5 + dj with g = (oc*3+ic)*5+di
    for (int i = tid; i < 450; i += NT) {
        int g = i / 5, dj = i - 5 * g;
        float w = w2[i];
        w2q[g * 6 + dj] = make_float2(w, w);
    }
    const float* xb = x + (size_t)b * 784;
    for (int i = tid; i < 784; i += NT) {
        int r = i / 28, c = i % 28;
        xpadT[(c + 2) * XPITCH + (r + 2)] = xb[i];
    }
    __syncthreads();

    // ---- conv1 (once): warps 0..5 ----
    if (warp < 6 && lane < 28) {
        int c = warp % 3, colbase = (warp / 3) * 14, row = lane;
        float wr[25];
        #pragma unroll
        for (int k = 0; k < 25; k++) wr[k] = __ldg(&w1[c * 25 + k]);
        float bias = __ldg(&b1[c]);
        float acc[14];
        #pragma unroll
        for (int j = 0; j < 14; j++) acc[j] = bias;
        #pragma unroll
        for (int di = 0; di < 5; di++) {
            float v[18];
            #pragma unroll
            for (int k = 0; k < 18; k++)
                v[k] = xpadT[(colbase + k) * XPITCH + row + di];
            #pragma unroll
            for (int j = 0; j < 14; j++)
                #pragma unroll
                for (int dj = 0; dj < 5; dj++)
                    acc[j] += v[j + dj] * wr[di * 5 + dj];
        }
        #pragma unroll
        for (int j = 0; j < 14; j++)
            c1s[c * 840 + (colbase + j) * C1CP + row] = acc[j];
    }
    __syncthreads();   // c1s complete before phase A reads it

    // ---- persistent register state ----
    const int  par  = lane & 1;             // oc parity within a pair
    const int  brow = lane >> 1;            // conv2 output row (0..13)
    // B warps 0..2: oc = 2*warp + par, packed cols j = 0..5
    const bool bwarp = (warp < 3);
    const bool bact  = bwarp && (lane < 28);
    const int  boc   = 2 * warp + par;
    float m2x[6], m2y[6];
    #pragma unroll
    for (int j = 0; j < 6; j++) { m2x[j] = 0.f; m2y[j] = 0.f; }
    const float b2r = bact ? __ldg(&b2[boc]) : 0.f;
    // warp 3: j=6 slice for all 3 oc-pairs (NO D work)
    const bool j6act = (warp == 3) && (lane < 28);
    float m36x[3], m36y[3], b2p[3];
    #pragma unroll
    for (int p = 0; p < 3; p++) {
        m36x[p] = 0.f; m36y[p] = 0.f;
        b2p[p] = j6act ? __ldg(&b2[2 * p + par]) : 0.f;
    }
    // A warps 4..6: channel c = warp-4, mem1 in regs; also D rows (4/4/2)
    const int  ach = warp - 4;
    float mr[28];
    #pragma unroll
    for (int i = 0; i < 28; i++) mr[i] = 0.f;
    const int  pi  = lane % 14;
    const int  dpj = lane / 14;
    const bool aact = (warp >= 4) && (lane < 28);
    const int  drow0 = (warp - 4) * 4;      // warp4:0, warp5:4, warp6:8
    const int  dcnt  = (warp == 6) ? 2 : 4;
    float m3[4], a3[4];
    #pragma unroll
    for (int r = 0; r < 4; r++) { m3[r] = 0.f; a3[r] = 0.f; }

    // Phase A: mem1 += c1, fire, 2x2 pool -> p1p[pb] paired layout
    auto phaseA = [&](int pb) {
        if (aact) {
            float* p1f = reinterpret_cast<float*>(p1p[pb]);
            #pragma unroll
            for (int i = 0; i < 7; i++) {
                int pj   = 2 * i + dpj;                 // pooled col 0..13
                int base = ach * 840 + (2 * pj) * C1CP + 2 * pi;
                float2 ca = *reinterpret_cast<const float2*>(&c1s[base]);
                float2 cb = *reinterpret_cast<const float2*>(&c1s[base + C1CP]);
                float m0 = mr[i * 4 + 0] + ca.x;
                float m1 = mr[i * 4 + 1] + ca.y;
                float m2 = mr[i * 4 + 2] + cb.x;
                float m3v = mr[i * 4 + 3] + cb.y;
                float s0 = (m0 >= TH) ? TH : 0.f;
                float s1 = (m1 >= TH) ? TH : 0.f;
                float s2 = (m2 >= TH) ? TH : 0.f;
                float s3 = (m3v >= TH) ? TH : 0.f;
                mr[i * 4 + 0] = m0 - s0;
                mr[i * 4 + 1] = m1 - s1;
                mr[i * 4 + 2] = m2 - s2;
                mr[i * 4 + 3] = m3v - s3;
                float val = 0.25f * (s0 + s1 + s2 + s3);
                int padcol = pj + 2;                    // 2..15
                int rbase  = (ach * P1ROWS + (pi + 2)) * P1K;
                if (padcol <= 13) p1f[(rbase + padcol) * 2]         = val;  // .x
                if (padcol >= 7)  p1f[(rbase + padcol - 7) * 2 + 1] = val;  // .y
            }
        }
    };

    // Phase D share (warps 4..6): fc + mem3 fire for rows [drow0, drow0+dcnt)
    auto phaseDsh = [&](int td) {
        const float* buf = s2P[td & 1];
        float pv[10];
        #pragma unroll
        for (int i = 0; i < 10; i++) {
            int k = lane + 32 * i;
            pv[i] = 0.f;
            if (k < 294) {
                float4 q = *reinterpret_cast<const float4*>(&buf[k * 4]);
                pv[i] = 0.25f * (q.x + q.y + q.z + q.w);
            }
        }
        #pragma unroll
        for (int rr = 0; rr < 4; rr++) {
            if (rr < dcnt) {
                int r = drow0 + rr;
                float part = 0.f;
                const float* wrow = wf + r * 294;
                #pragma unroll
                for (int i = 0; i < 10; i++) {
                    int k = lane + 32 * i;
                    if (k < 294) part += pv[i] * __ldg(&wrow[k]);
                }
                #pragma unroll
                for (int s = 16; s > 0; s >>= 1)
                    part += __shfl_xor_sync(0xffffffffu, part, s);
                float m  = m3[rr] + part + __ldg(&bf[r]);
                float sp = (m >= TH) ? TH : 0.f;
                m3[rr] = m - sp;
                a3[rr] += sp;
                if (lane == 0) {
                    if (td == 3) out[(size_t)b * 10 + r] = a3[rr] * 0.25f;
                    if (td == 7) out[(size_t)nb * 10 + (size_t)b * 10 + r] = a3[rr] * 0.125f;
                }
            }
        }
    };

    phaseA(0);           // p1 for t=0 (warps 4-6)
    __syncthreads();

    // ---- pipelined time loop: ONE barrier per timestep ----
    for (int t = 0; t < TSTEPS; t++) {
        if (bwarp) {
            // B(t) cols j=0..5: reads p1p[t&1], writes s2P[t&1]
            if (lane < 28) {
                const float2* p1 = p1p[t & 1];
                unsigned long long A2[6];
                unsigned long long bini = pk2(b2r, b2r);
                #pragma unroll
                for (int j = 0; j < 6; j++) A2[j] = bini;
                #pragma unroll
                for (int ic = 0; ic < 3; ic++) {
                    #pragma unroll
                    for (int di = 0; di < 5; di++) {
                        const float2* src = &p1[(ic * P1ROWS + brow + di) * P1K];
                        ulonglong2 u0 = *reinterpret_cast<const ulonglong2*>(src);
                        ulonglong2 u1 = *reinterpret_cast<const ulonglong2*>(src + 2);
                        ulonglong2 u2 = *reinterpret_cast<const ulonglong2*>(src + 4);
                        ulonglong2 u3 = *reinterpret_cast<const ulonglong2*>(src + 6);
                        ulonglong2 u4 = *reinterpret_cast<const ulonglong2*>(src + 8);
                        unsigned long long pv[10] = {u0.x, u0.y, u1.x, u1.y, u2.x,
                                                     u2.y, u3.x, u3.y, u4.x, u4.y};
                        const int g = (boc * 3 + ic) * 5 + di;
                        const float2* wp = &w2q[g * 6];
                        ulonglong2 wA = *reinterpret_cast<const ulonglong2*>(wp);
                        ulonglong2 wB = *reinterpret_cast<const ulonglong2*>(wp + 2);
                        unsigned long long w4v =
                            *reinterpret_cast<const unsigned long long*>(wp + 4);
                        unsigned long long wv[5] = {wA.x, wA.y, wB.x, wB.y, w4v};
                        #pragma unroll
                        for (int dj = 0; dj < 5; dj++)
                            #pragma unroll
                            for (int j = 0; j < 6; j++)
                                fma2(A2[j], pv[j + dj], wv[dj]);
                    }
                }
                float* sdst = s2P[t & 1];
                const int obase = boc * 196;
                #pragma unroll
                for (int j = 0; j < 6; j++) {
                    float2 q = upk(A2[j]);
                    {
                        float m  = m2x[j] + q.x;
                        float sp = (m >= TH) ? TH : 0.f;
                        m2x[j]   = m - sp;
                        int cc = j;
                        sdst[obase + ((brow >> 1) * 7 + (cc >> 1)) * 4 +
                             (brow & 1) * 2 + (cc & 1)] = sp;
                    }
                    {
                        float m  = m2y[j] + q.y;
                        float sp = (m >= TH) ? TH : 0.f;
                        m2y[j]   = m - sp;
                        int cc = j + 7;
                        sdst[obase + ((brow >> 1) * 7 + (cc >> 1)) * 4 +
                             (brow & 1) * 2 + (cc & 1)] = sp;
                    }
                }
            }
        } else if (warp == 3) {
            // B(t) col j=6 only — interleaved chains, per-dj broadcast weights
            if (j6act) {
                const float2* p1 = p1p[t & 1];
                const unsigned long long* wq64 =
                    reinterpret_cast<const unsigned long long*>(w2q);
                unsigned long long G0 = pk2(b2p[0], b2p[0]);
                unsigned long long G1 = pk2(b2p[1], b2p[1]);
                unsigned long long G2 = pk2(b2p[2], b2p[2]);
                #pragma unroll
                for (int ic = 0; ic < 3; ic++) {
                    #pragma unroll
                    for (int di = 0; di < 5; di++) {
                        const float2* src = &p1[(ic * P1ROWS + brow + di) * P1K];
                        ulonglong2 u3 = *reinterpret_cast<const ulonglong2*>(src + 6);
                        ulonglong2 u4 = *reinterpret_cast<const ulonglong2*>(src + 8);
                        unsigned long long p10 =
                            *reinterpret_cast<const unsigned long long*>(src + 10);
                        unsigned long long pv6[5] = {u3.x, u3.y, u4.x, u4.y, p10};
                        const int g0 = (((par)     * 3 + ic) * 5 + di) * 6;
                        const int g1 = (((2 + par) * 3 + ic) * 5 + di) * 6;
                        const int g2 = (((4 + par) * 3 + ic) * 5 + di) * 6;
                        #pragma unroll
                        for (int dj = 0; dj < 5; dj++) {
                            fma2(G0, pv6[dj], wq64[g0 + dj]);  // 3 indep chains
                            fma2(G1, pv6[dj], wq64[g1 + dj]);
                            fma2(G2, pv6[dj], wq64[g2 + dj]);
                        }
                    }
                }
                float* sdst = s2P[t & 1];
                unsigned long long Gs[3] = {G0, G1, G2};
                #pragma unroll
                for (int p = 0; p < 3; p++) {
                    const int oc = 2 * p + par;
                    const int obase = oc * 196;
                    float2 q = upk(Gs[p]);
                    {
                        float m  = m36x[p] + q.x;
                        float sp = (m >= TH) ? TH : 0.f;
                        m36x[p]  = m - sp;
                        // cc = 6 -> group 3, sub (brow&1)*2+0
                        sdst[obase + ((brow >> 1) * 7 + 3) * 4 +
                             (brow & 1) * 2 + 0] = sp;
                    }
                    {
                        float m  = m36y[p] + q.y;
                        float sp = (m >= TH) ? TH : 0.f;
                        m36y[p]  = m - sp;
                        // cc = 13 -> group 6, sub (brow&1)*2+1
                        sdst[obase + ((brow >> 1) * 7 + 6) * 4 +
                             (brow & 1) * 2 + 1] = sp;
                    }
                }
            }
        } else {
            // warps 4-6: D(t-1) rows share, then A(t+1)
            if (t > 0) phaseDsh(t - 1);
            if (t < TSTEPS - 1) phaseA((t + 1) & 1);
        }
        __syncthreads();
    }
    // epilogue: D for the last timestep
    if (warp >= 4) phaseDsh(TSTEPS - 1);
}

extern "C" void kernel_launch(void* const* d_in, const int* in_sizes, int n_in,
                              void* d_out, int out_size)
{
    const float* x  = (const float*)d_in[0];
    const float* w1 = (const float*)d_in[1];
    const float* b1 = (const float*)d_in[2];
    const float* w2 = (const float*)d_in[3];
    const float* b2 = (const float*)d_in[4];
    const float* wf = (const float*)d_in[5];
    const float* bf = (const float*)d_in[6];
    float* out = (float*)d_out;

    int nb = in_sizes[0] / 784;   // 4096
    snn_kernel<<<nb, NT>>>(x, w1, b1, w2, b2, wf, bf, out, nb);
}